// round 1
// baseline (speedup 1.0000x reference)
#include <cuda_runtime.h>
#include <cuda_bf16.h>
#include <math.h>

#define H 512
#define W 512
#define NPIX (H * W)

// Scratch (allocation-free rule: __device__ globals)
__device__ unsigned char d_S[NPIX];    // surface of pred
__device__ unsigned char d_Sp[NPIX];   // surface of gt
__device__ float d_g2A[NPIX];          // squared col-dist field for feature S   (-> dta)
__device__ float d_g2B[NPIX];          // squared col-dist field for feature S'  (-> dtb)
__device__ float d_rowNum[H];
__device__ float d_rowDen[H];

// ---------------------------------------------------------------------------
// Kernel 1: binarize + erode + surface masks
// S  = p & ~erode(p), erode = center & 4-neighbors (OOB = false)
// ---------------------------------------------------------------------------
__global__ void k_masks(const float* __restrict__ pred, const float* __restrict__ gt) {
    int idx = blockIdx.x * blockDim.x + threadIdx.x;
    if (idx >= NPIX) return;
    int r = idx >> 9;
    int c = idx & (W - 1);

    // pred
    {
        bool ctr = pred[idx] != 0.0f;
        bool up = (r > 0)     && (pred[idx - W] != 0.0f);
        bool dn = (r < H - 1) && (pred[idx + W] != 0.0f);
        bool lt = (c > 0)     && (pred[idx - 1] != 0.0f);
        bool rt = (c < W - 1) && (pred[idx + 1] != 0.0f);
        d_S[idx] = (unsigned char)(ctr && !(up && dn && lt && rt));
    }
    // gt
    {
        bool ctr = gt[idx] != 0.0f;
        bool up = (r > 0)     && (gt[idx - W] != 0.0f);
        bool dn = (r < H - 1) && (gt[idx + W] != 0.0f);
        bool lt = (c > 0)     && (gt[idx - 1] != 0.0f);
        bool rt = (c < W - 1) && (gt[idx + 1] != 0.0f);
        d_Sp[idx] = (unsigned char)(ctr && !(up && dn && lt && rt));
    }
}

// ---------------------------------------------------------------------------
// Kernel 2: per-column vertical distance sweeps (exact mirror of the
// reference lax.scan: carry starts at 1e6, c = feat ? 0 : carry+1).
// Block 0 -> feature S (g2A), block 1 -> feature S' (g2B).
// Each thread owns one column; accesses are coalesced across threads.
// ---------------------------------------------------------------------------
__global__ void k_colsweep() {
    const unsigned char* __restrict__ feat = (blockIdx.x == 0) ? d_S : d_Sp;
    float* __restrict__ g2 = (blockIdx.x == 0) ? d_g2A : d_g2B;
    int c = threadIdx.x;

    float df = 1e6f;
    #pragma unroll 8
    for (int r = 0; r < H; ++r) {
        int i = r * W + c;
        df = feat[i] ? 0.0f : (df + 1.0f);
        g2[i] = df;  // store df temporarily
    }
    float db = 1e6f;
    #pragma unroll 8
    for (int r = H - 1; r >= 0; --r) {
        int i = r * W + c;
        db = feat[i] ? 0.0f : (db + 1.0f);
        float m = fminf(g2[i], db);
        g2[i] = m * m;
    }
}

// ---------------------------------------------------------------------------
// Kernel 3: row min-plus (exact, early-exit outward scan) + masked sums.
// One block per row. d2(c) = min_j g2[j] + (c-j)^2; scanning Delta outward
// and breaking at Delta^2 >= best is exact because g2 >= 0.
// Deterministic block tree-reduce -> per-row partials.
// ---------------------------------------------------------------------------
__device__ __forceinline__ float edt_at(const float* __restrict__ g2row, int c) {
    float best = g2row[c];
    #pragma unroll 4
    for (int d = 1; d < W; ++d) {
        float dd = (float)(d * d);
        if (dd >= best) break;
        int jl = c - d;
        int jr = c + d;
        if (jl >= 0) best = fminf(best, g2row[jl] + dd);
        if (jr < W)  best = fminf(best, g2row[jr] + dd);
    }
    return sqrtf(best);
}

__global__ void k_rowpass() {
    __shared__ float sA[W];   // g2 row for feature S   (dta)
    __shared__ float sB[W];   // g2 row for feature S'  (dtb)
    __shared__ float sNum[W];
    __shared__ float sDen[W];

    int r = blockIdx.x;
    int c = threadIdx.x;
    int i = r * W + c;

    sA[c] = d_g2A[i];
    sB[c] = d_g2B[i];
    __syncthreads();

    float num = 0.0f;
    float den = 0.0f;

    if (d_Sp[i]) {               // dta sampled on S'
        num += edt_at(sA, c);
        den += 1.0f;
    }
    if (d_S[i]) {                // dtb sampled on S
        num += edt_at(sB, c);
        den += 1.0f;
    }

    sNum[c] = num;
    sDen[c] = den;
    __syncthreads();

    // deterministic tree reduction over 512 threads
    for (int s = W / 2; s > 0; s >>= 1) {
        if (c < s) {
            sNum[c] += sNum[c + s];
            sDen[c] += sDen[c + s];
        }
        __syncthreads();
    }
    if (c == 0) {
        d_rowNum[r] = sNum[0];
        d_rowDen[r] = sDen[0];
    }
}

// ---------------------------------------------------------------------------
// Kernel 4: final fold of 512 row partials -> scalar output
// ---------------------------------------------------------------------------
__global__ void k_final(float* __restrict__ out) {
    __shared__ float sNum[H];
    __shared__ float sDen[H];
    int t = threadIdx.x;
    sNum[t] = d_rowNum[t];
    sDen[t] = d_rowDen[t];
    __syncthreads();
    for (int s = H / 2; s > 0; s >>= 1) {
        if (t < s) {
            sNum[t] += sNum[t + s];
            sDen[t] += sDen[t + s];
        }
        __syncthreads();
    }
    if (t == 0) out[0] = sNum[0] / sDen[0];
}

extern "C" void kernel_launch(void* const* d_in, const int* in_sizes, int n_in,
                              void* d_out, int out_size) {
    const float* pred = (const float*)d_in[0];
    const float* gt   = (const float*)d_in[1];
    float* out = (float*)d_out;

    k_masks<<<NPIX / 256, 256>>>(pred, gt);
    k_colsweep<<<2, W>>>();
    k_rowpass<<<H, W>>>();
    k_final<<<1, H>>>(out);
}

// round 2
// speedup vs baseline: 11.9032x; 11.9032x over previous
#include <cuda_runtime.h>
#include <cuda_bf16.h>
#include <math.h>

#define H 512
#define W 512
#define NPIX (H * W)

// Scratch (allocation-free rule: __device__ globals)
__device__ unsigned char d_S[NPIX];    // surface of pred
__device__ unsigned char d_Sp[NPIX];   // surface of gt
__device__ float d_rowNum[H];
__device__ float d_rowDen[H];
__device__ unsigned int d_cnt;         // zero-initialized; atomicInc wraps -> self-resetting

// ---------------------------------------------------------------------------
// Kernel 1: binarize + erode + surface masks
// S = p & ~erode(p), erode = center & 4 cross-neighbors (OOB = false)
// ---------------------------------------------------------------------------
__global__ void k_masks(const float* __restrict__ pred, const float* __restrict__ gt) {
    int idx = blockIdx.x * blockDim.x + threadIdx.x;
    if (idx >= NPIX) return;
    int r = idx >> 9;
    int c = idx & (W - 1);

    {
        bool ctr = pred[idx] != 0.0f;
        bool up = (r > 0)     && (pred[idx - W] != 0.0f);
        bool dn = (r < H - 1) && (pred[idx + W] != 0.0f);
        bool lt = (c > 0)     && (pred[idx - 1] != 0.0f);
        bool rt = (c < W - 1) && (pred[idx + 1] != 0.0f);
        d_S[idx] = (unsigned char)(ctr && !(up && dn && lt && rt));
    }
    {
        bool ctr = gt[idx] != 0.0f;
        bool up = (r > 0)     && (gt[idx - W] != 0.0f);
        bool dn = (r < H - 1) && (gt[idx + W] != 0.0f);
        bool lt = (c > 0)     && (gt[idx - 1] != 0.0f);
        bool rt = (c < W - 1) && (gt[idx + 1] != 0.0f);
        d_Sp[idx] = (unsigned char)(ctr && !(up && dn && lt && rt));
    }
}

// ---------------------------------------------------------------------------
// Exact vertical squared distance to nearest feature in this column.
// Outward scan: the first hit at offset k IS the minimum (offsets increase).
// Empty column -> 1e12 (matches reference's BIG^2 scale; dominated anyway).
// Loads are coalesced across threads (consecutive c, same row offset).
// ---------------------------------------------------------------------------
__device__ __forceinline__ float vdist2(const unsigned char* __restrict__ feat,
                                        int r, int c) {
    if (feat[r * W + c]) return 0.0f;
    #pragma unroll 4
    for (int k = 1; k < H; ++k) {
        bool hit = false;
        int ru = r - k, rd = r + k;
        if (ru >= 0) hit = (feat[ru * W + c] != 0);
        if (!hit && rd < H) hit = (feat[rd * W + c] != 0);
        if (hit) return (float)(k * k);
    }
    return 1e12f;
}

// ---------------------------------------------------------------------------
// Exact row min-plus with early exit: d2(c) = min_j g2[j] + (c-j)^2.
// Scanning |c-j| outward and breaking at (c-j)^2 >= best is exact (g2 >= 0).
// ---------------------------------------------------------------------------
__device__ __forceinline__ float edt_at(const float* __restrict__ g2row, int c) {
    float best = g2row[c];
    #pragma unroll 4
    for (int d = 1; d < W; ++d) {
        float dd = (float)(d * d);
        if (dd >= best) break;
        int jl = c - d;
        int jr = c + d;
        if (jl >= 0) best = fminf(best, g2row[jl] + dd);
        if (jr < W)  best = fminf(best, g2row[jr] + dd);
    }
    return sqrtf(best);
}

// ---------------------------------------------------------------------------
// Fused kernel: one block per row.
//  - per-thread exact vertical distance (both features) into shared
//  - exact row min-plus at pixels where the OTHER surface mask is set
//  - deterministic block tree-reduce -> row partials
//  - last finished block folds the 512 row partials -> scalar out
// ---------------------------------------------------------------------------
__global__ void k_fused(float* __restrict__ out) {
    __shared__ float sA[W];   // g2 for feature S   (-> dta)
    __shared__ float sB[W];   // g2 for feature S'  (-> dtb)
    __shared__ float sNum[W];
    __shared__ float sDen[W];
    __shared__ bool  isLast;

    int r = blockIdx.x;
    int c = threadIdx.x;
    int i = r * W + c;

    sA[c] = vdist2(d_S,  r, c);
    sB[c] = vdist2(d_Sp, r, c);
    bool onSp = (d_Sp[i] != 0);
    bool onS  = (d_S[i]  != 0);
    __syncthreads();

    float num = 0.0f;
    float den = 0.0f;
    if (onSp) { num += edt_at(sA, c); den += 1.0f; }  // dta sampled on S'
    if (onS)  { num += edt_at(sB, c); den += 1.0f; }  // dtb sampled on S

    sNum[c] = num;
    sDen[c] = den;
    __syncthreads();

    // deterministic tree reduction over 512 threads
    for (int s = W / 2; s > 0; s >>= 1) {
        if (c < s) {
            sNum[c] += sNum[c + s];
            sDen[c] += sDen[c + s];
        }
        __syncthreads();
    }

    if (c == 0) {
        d_rowNum[r] = sNum[0];
        d_rowDen[r] = sDen[0];
        __threadfence();
        unsigned int old = atomicInc(&d_cnt, H - 1);  // wraps to 0 -> self-reset
        isLast = (old == H - 1);
    }
    __syncthreads();

    if (isLast) {
        // fold 512 row partials (deterministic order)
        sNum[c] = d_rowNum[c];
        sDen[c] = d_rowDen[c];
        __syncthreads();
        for (int s = H / 2; s > 0; s >>= 1) {
            if (c < s) {
                sNum[c] += sNum[c + s];
                sDen[c] += sDen[c + s];
            }
            __syncthreads();
        }
        if (c == 0) out[0] = sNum[0] / sDen[0];
    }
}

extern "C" void kernel_launch(void* const* d_in, const int* in_sizes, int n_in,
                              void* d_out, int out_size) {
    const float* pred = (const float*)d_in[0];
    const float* gt   = (const float*)d_in[1];
    float* out = (float*)d_out;

    k_masks<<<NPIX / 256, 256>>>(pred, gt);
    k_fused<<<H, W>>>(out);
}

// round 3
// speedup vs baseline: 15.7218x; 1.3208x over previous
#include <cuda_runtime.h>
#include <cuda_bf16.h>
#include <math.h>

#define H 512
#define W 512
#define NPIX (H * W)

// Scratch (allocation-free rule: __device__ globals)
__device__ unsigned char d_S[NPIX];    // surface of pred
__device__ unsigned char d_Sp[NPIX];   // surface of gt
__device__ float d_rowNum[H];
__device__ float d_rowDen[H];
__device__ unsigned int d_cnt;         // zero-init; atomicInc wraps -> self-resetting

// ---------------------------------------------------------------------------
// Kernel 1: binarize + erode + surface masks
// ---------------------------------------------------------------------------
__global__ void k_masks(const float* __restrict__ pred, const float* __restrict__ gt) {
    int idx = blockIdx.x * blockDim.x + threadIdx.x;
    if (idx >= NPIX) return;
    int r = idx >> 9;
    int c = idx & (W - 1);

    {
        bool ctr = pred[idx] != 0.0f;
        bool up = (r > 0)     && (pred[idx - W] != 0.0f);
        bool dn = (r < H - 1) && (pred[idx + W] != 0.0f);
        bool lt = (c > 0)     && (pred[idx - 1] != 0.0f);
        bool rt = (c < W - 1) && (pred[idx + 1] != 0.0f);
        d_S[idx] = (unsigned char)(ctr && !(up && dn && lt && rt));
    }
    {
        bool ctr = gt[idx] != 0.0f;
        bool up = (r > 0)     && (gt[idx - W] != 0.0f);
        bool dn = (r < H - 1) && (gt[idx + W] != 0.0f);
        bool lt = (c > 0)     && (gt[idx - 1] != 0.0f);
        bool rt = (c < W - 1) && (gt[idx + 1] != 0.0f);
        d_Sp[idx] = (unsigned char)(ctr && !(up && dn && lt && rt));
    }
}

#define KP 6   // parallel vertical probe depth; P(miss) ~ 5e-4 per pixel

// Serial exact fallback for the rare pixel with no vertical hit within +-KP.
__device__ __noinline__ float vdist2_far(const unsigned char* __restrict__ feat,
                                         int r, int c) {
    for (int k = KP + 1; k < H; ++k) {
        bool hit = false;
        int ru = r - k, rd = r + k;
        if (ru >= 0) hit = (feat[ru * W + c] != 0);
        if (!hit && rd < H) hit = (feat[rd * W + c] != 0);
        if (hit) return (float)(k * k);
    }
    return 1e12f;
}

// ---------------------------------------------------------------------------
// Fused kernel: one block per row.
// ---------------------------------------------------------------------------
__global__ void __launch_bounds__(W) k_fused(float* __restrict__ out) {
    __shared__ float sA[W];     // g2 for feature S   (-> dta)
    __shared__ float sB[W];     // g2 for feature S'  (-> dtb)
    __shared__ float wNum[16];
    __shared__ float wDen[16];
    __shared__ bool  isLast;

    const int r = blockIdx.x;
    const int c = threadIdx.x;
    const int i = r * W + c;
    const int lane = c & 31;
    const int wid = c >> 5;

    // --- vertical distance: batched parallel probes, both features at once ---
    bool onS  = (d_S[i]  != 0);
    bool onSp = (d_Sp[i] != 0);

    unsigned hitsA = 0, hitsB = 0;
    #pragma unroll
    for (int k = 1; k <= KP; ++k) {
        int ru = r - k, rd = r + k;
        bool au = (ru >= 0) && (d_S [ru * W + c] != 0);
        bool ad = (rd <  H) && (d_S [rd * W + c] != 0);
        bool bu = (ru >= 0) && (d_Sp[ru * W + c] != 0);
        bool bd = (rd <  H) && (d_Sp[rd * W + c] != 0);
        if (au | ad) hitsA |= 1u << k;
        if (bu | bd) hitsB |= 1u << k;
    }

    float g2A, g2B;
    if (onS) g2A = 0.0f;
    else if (hitsA) { int k = __ffs(hitsA) - 1; g2A = (float)(k * k); }
    else g2A = vdist2_far(d_S, r, c);

    if (onSp) g2B = 0.0f;
    else if (hitsB) { int k = __ffs(hitsB) - 1; g2B = (float)(k * k); }
    else g2B = vdist2_far(d_Sp, r, c);

    sA[c] = g2A;
    sB[c] = g2B;
    __syncthreads();

    // --- exact row min-plus with batched head + early-exit tail ---
    float num = 0.0f;
    float den = 0.0f;

    if (onSp) {   // dta sampled on S'
        float best = sA[c];
        #pragma unroll
        for (int d = 1; d <= 3; ++d) {
            float dd = (float)(d * d);
            if (c - d >= 0) best = fminf(best, sA[c - d] + dd);
            if (c + d <  W) best = fminf(best, sA[c + d] + dd);
        }
        for (int d = 4; d < W; ++d) {
            float dd = (float)(d * d);
            if (dd >= best) break;
            if (c - d >= 0) best = fminf(best, sA[c - d] + dd);
            if (c + d <  W) best = fminf(best, sA[c + d] + dd);
        }
        num += sqrtf(best);
        den += 1.0f;
    }
    if (onS) {    // dtb sampled on S
        float best = sB[c];
        #pragma unroll
        for (int d = 1; d <= 3; ++d) {
            float dd = (float)(d * d);
            if (c - d >= 0) best = fminf(best, sB[c - d] + dd);
            if (c + d <  W) best = fminf(best, sB[c + d] + dd);
        }
        for (int d = 4; d < W; ++d) {
            float dd = (float)(d * d);
            if (dd >= best) break;
            if (c - d >= 0) best = fminf(best, sB[c - d] + dd);
            if (c + d <  W) best = fminf(best, sB[c + d] + dd);
        }
        num += sqrtf(best);
        den += 1.0f;
    }

    // --- warp shuffle reduction (deterministic) ---
    #pragma unroll
    for (int off = 16; off > 0; off >>= 1) {
        num += __shfl_down_sync(0xFFFFFFFFu, num, off);
        den += __shfl_down_sync(0xFFFFFFFFu, den, off);
    }
    if (lane == 0) { wNum[wid] = num; wDen[wid] = den; }
    __syncthreads();

    if (wid == 0) {
        float n = (lane < 16) ? wNum[lane] : 0.0f;
        float d = (lane < 16) ? wDen[lane] : 0.0f;
        #pragma unroll
        for (int off = 8; off > 0; off >>= 1) {
            n += __shfl_down_sync(0xFFFFFFFFu, n, off);
            d += __shfl_down_sync(0xFFFFFFFFu, d, off);
        }
        if (lane == 0) {
            d_rowNum[r] = n;
            d_rowDen[r] = d;
            __threadfence();
            unsigned int old = atomicInc(&d_cnt, H - 1);  // wraps -> self-reset
            isLast = (old == H - 1);
        }
    }
    __syncthreads();

    // --- last block folds the 512 row partials ---
    if (isLast) {
        float n = d_rowNum[c];
        float d = d_rowDen[c];
        #pragma unroll
        for (int off = 16; off > 0; off >>= 1) {
            n += __shfl_down_sync(0xFFFFFFFFu, n, off);
            d += __shfl_down_sync(0xFFFFFFFFu, d, off);
        }
        if (lane == 0) { wNum[wid] = n; wDen[wid] = d; }
        __syncthreads();
        if (wid == 0) {
            float nn = (lane < 16) ? wNum[lane] : 0.0f;
            float dd = (lane < 16) ? wDen[lane] : 0.0f;
            #pragma unroll
            for (int off = 8; off > 0; off >>= 1) {
                nn += __shfl_down_sync(0xFFFFFFFFu, nn, off);
                dd += __shfl_down_sync(0xFFFFFFFFu, dd, off);
            }
            if (lane == 0) out[0] = nn / dd;
        }
    }
}

extern "C" void kernel_launch(void* const* d_in, const int* in_sizes, int n_in,
                              void* d_out, int out_size) {
    const float* pred = (const float*)d_in[0];
    const float* gt   = (const float*)d_in[1];
    float* out = (float*)d_out;

    k_masks<<<NPIX / 256, 256>>>(pred, gt);
    k_fused<<<H, W>>>(out);
}